// round 1
// baseline (speedup 1.0000x reference)
#include <cuda_runtime.h>

// BehaviorEngine: per-pixel self-pattern + MLP(33->64 relu ->32) + alpha*g
// H=W=1024, D=32, HID=64. One thread per pixel, 128 threads/block.
// FP32 throughout; MLP inner products use packed fma.rn.f32x2 (SASS FFMA2).

#define HW_PIX   (1024*1024)
#define NTHREADS 128
#define EPSF     1e-8f
#define ALPHAF   0.3f
#define PATW     0.1f

__device__ __forceinline__ unsigned long long ffma2(unsigned long long a,
                                                    unsigned long long b,
                                                    unsigned long long c) {
    unsigned long long d;
    asm("fma.rn.f32x2 %0, %1, %2, %3;" : "=l"(d) : "l"(a), "l"(b), "l"(c));
    return d;
}
__device__ __forceinline__ unsigned long long pack_dup(float x) {
    unsigned long long d;
    asm("mov.b64 %0, {%1, %1};" : "=l"(d) : "f"(x));
    return d;
}
__device__ __forceinline__ unsigned long long pack2(float lo, float hi) {
    unsigned long long d;
    asm("mov.b64 %0, {%1, %2};" : "=l"(d) : "f"(lo), "f"(hi));
    return d;
}
__device__ __forceinline__ void unpack2(unsigned long long v, float& lo, float& hi) {
    asm("mov.b64 {%0, %1}, %2;" : "=f"(lo), "=f"(hi) : "l"(v));
}

__global__ void __launch_bounds__(NTHREADS)
be_kernel(const float* __restrict__ grid, const float* __restrict__ pot,
          const float* __restrict__ W1,   const float* __restrict__ b1,
          const float* __restrict__ W2,   const float* __restrict__ b2,
          float* __restrict__ out)
{
    __shared__ __align__(16) float sW1[33 * 64];   // [c][f], f contiguous
    __shared__ __align__(16) float sW2[64 * 32];   // [f][d], d contiguous
    __shared__ __align__(16) float sB1[64];
    __shared__ __align__(16) float sB2[32];
    __shared__ float sX[NTHREADS * 33];            // per-thread x vec, stride 33 (conflict-free)

    const int tid = threadIdx.x;

    // Cooperative weight staging
    for (int i = tid; i < 33 * 64; i += NTHREADS) sW1[i] = W1[i];
    for (int i = tid; i < 64 * 32; i += NTHREADS) sW2[i] = W2[i];
    if (tid < 64) sB1[tid] = b1[tid];
    if (tid < 32) sB2[tid] = b2[tid];

    const size_t p = (size_t)blockIdx.x * NTHREADS + tid;
    const float4* g4 = (const float4*)(grid + p * 32);
    float4 gv[8];
    #pragma unroll
    for (int k = 0; k < 8; k++) gv[k] = g4[k];      // LDG overlaps the barrier
    const float potv = pot[p];

    __syncthreads();

    float g[32];
    #pragma unroll
    for (int k = 0; k < 8; k++) {
        g[4 * k + 0] = gv[k].x; g[4 * k + 1] = gv[k].y;
        g[4 * k + 2] = gv[k].z; g[4 * k + 3] = gv[k].w;
    }

    // norms: ||g|| and ||g^3||
    float gn2 = 0.f, cn2 = 0.f;
    #pragma unroll
    for (int i = 0; i < 32; i++) {
        float q  = g[i] * g[i];
        gn2 += q;
        float c3 = q * g[i];
        cn2 = fmaf(c3, c3, cn2);
    }
    const float t = PATW * sqrtf(gn2) / (sqrtf(cn2) + EPSF);

    // x = g + t*g^3 -> shared stage;  out-acc pre-init with b2 + alpha*g
    float* myX = sX + tid * 33;
    unsigned long long oacc[16];
    #pragma unroll
    for (int i = 0; i < 32; i += 2) {
        float q0 = g[i] * g[i];
        float q1 = g[i + 1] * g[i + 1];
        myX[i]     = fmaf(t * q0, g[i],     g[i]);
        myX[i + 1] = fmaf(t * q1, g[i + 1], g[i + 1]);
        oacc[i >> 1] = pack2(fmaf(ALPHAF, g[i],     sB2[i]),
                             fmaf(ALPHAF, g[i + 1], sB2[i + 1]));
    }
    myX[32] = potv;

    // Layer 1: h[64] = relu(x . W1 + b1), h kept as 32 packed f32x2 accumulators
    unsigned long long h2[32];
    const unsigned long long* b1p = (const unsigned long long*)sB1;
    #pragma unroll
    for (int j = 0; j < 32; j++) h2[j] = b1p[j];

    #pragma unroll 1
    for (int c = 0; c < 33; c++) {
        const unsigned long long xc2 = pack_dup(myX[c]);       // broadcast-free scalar LDS
        const ulonglong2* wr = (const ulonglong2*)(sW1 + c * 64);
        #pragma unroll
        for (int j = 0; j < 16; j++) {
            ulonglong2 w = wr[j];                              // LDS.128 (warp broadcast)
            h2[2 * j]     = ffma2(xc2, w.x, h2[2 * j]);
            h2[2 * j + 1] = ffma2(xc2, w.y, h2[2 * j + 1]);
        }
    }

    // Layer 2: out[32] += relu(h) . W2   (f-loop fully unrolled; h stays in regs)
    #pragma unroll
    for (int j = 0; j < 32; j++) {
        float lo, hi;
        unpack2(h2[j], lo, hi);
        lo = fmaxf(lo, 0.f);
        hi = fmaxf(hi, 0.f);
        {
            const unsigned long long hl = pack_dup(lo);
            const ulonglong2* wr = (const ulonglong2*)(sW2 + (2 * j) * 32);
            #pragma unroll
            for (int q = 0; q < 8; q++) {
                ulonglong2 w = wr[q];
                oacc[2 * q]     = ffma2(hl, w.x, oacc[2 * q]);
                oacc[2 * q + 1] = ffma2(hl, w.y, oacc[2 * q + 1]);
            }
        }
        {
            const unsigned long long hh = pack_dup(hi);
            const ulonglong2* wr = (const ulonglong2*)(sW2 + (2 * j + 1) * 32);
            #pragma unroll
            for (int q = 0; q < 8; q++) {
                ulonglong2 w = wr[q];
                oacc[2 * q]     = ffma2(hh, w.x, oacc[2 * q]);
                oacc[2 * q + 1] = ffma2(hh, w.y, oacc[2 * q + 1]);
            }
        }
    }

    float4* o4 = (float4*)(out + p * 32);
    #pragma unroll
    for (int k = 0; k < 8; k++) {
        float a, b, c, d;
        unpack2(oacc[2 * k],     a, b);
        unpack2(oacc[2 * k + 1], c, d);
        o4[k] = make_float4(a, b, c, d);
    }
}

extern "C" void kernel_launch(void* const* d_in, const int* in_sizes, int n_in,
                              void* d_out, int out_size) {
    const float* grid = (const float*)d_in[0];
    const float* pot  = (const float*)d_in[1];
    const float* W1   = (const float*)d_in[2];
    const float* b1   = (const float*)d_in[3];
    const float* W2   = (const float*)d_in[4];
    const float* b2   = (const float*)d_in[5];
    float* out = (float*)d_out;

    const int blocks = HW_PIX / NTHREADS;   // 8192
    be_kernel<<<blocks, NTHREADS>>>(grid, pot, W1, b1, W2, b2, out);
}